// round 2
// baseline (speedup 1.0000x reference)
#include <cuda_runtime.h>
#include <math.h>

// Problem constants
#define BATCH 2
#define SEQ   2048
#define HID   2048
#define NHEAD 16
#define HDIM  128
#define FFD   8192
#define ROWS  (BATCH*SEQ)       // 4096
#define RMS_EPS 1e-5f

// ---------------------------------------------------------------------------
// Scratch (static __device__ arrays — allocation-free per harness rules)
// ---------------------------------------------------------------------------
__device__ float g_qn [ROWS*HID];
__device__ float g_q  [ROWS*HID];
__device__ float g_k  [ROWS*HID];
__device__ float g_v  [ROWS*HID];
__device__ float g_att[ROWS*HID];
__device__ float g_mod[ROWS*HID];
__device__ float g_t1 [ROWS*HID];
__device__ float g_t2 [ROWS*HID];
__device__ float g_x  [ROWS*HID];
__device__ float g_h  [ROWS*HID];
__device__ float g_gate[(size_t)ROWS*FFD];
__device__ float g_up  [(size_t)ROWS*FFD];
__device__ float g_sc  [(size_t)BATCH*NHEAD*SEQ*SEQ];   // 512 MB attention scores

// ---------------------------------------------------------------------------
// Reductions (blockDim.x == 256 assumed)
// ---------------------------------------------------------------------------
__device__ __forceinline__ float warpReduceSum(float v) {
#pragma unroll
    for (int o = 16; o; o >>= 1) v += __shfl_xor_sync(0xffffffffu, v, o);
    return v;
}
__device__ __forceinline__ float warpReduceMax(float v) {
#pragma unroll
    for (int o = 16; o; o >>= 1) v = fmaxf(v, __shfl_xor_sync(0xffffffffu, v, o));
    return v;
}
__device__ __forceinline__ float blockReduceSum256(float v) {
    __shared__ float sh[8];
    v = warpReduceSum(v);
    __syncthreads();
    if ((threadIdx.x & 31) == 0) sh[threadIdx.x >> 5] = v;
    __syncthreads();
    float r = 0.f;
#pragma unroll
    for (int i = 0; i < 8; i++) r += sh[i];
    return r;
}
__device__ __forceinline__ float blockReduceMax256(float v) {
    __shared__ float sh[8];
    v = warpReduceMax(v);
    __syncthreads();
    if ((threadIdx.x & 31) == 0) sh[threadIdx.x >> 5] = v;
    __syncthreads();
    float r = sh[0];
#pragma unroll
    for (int i = 1; i < 8; i++) r = fmaxf(r, sh[i]);
    return r;
}

// ---------------------------------------------------------------------------
// SGEMM: C = alpha * A * op(B)
//   A: [M,K] row-major, lda = row stride
//   BT=true : B is [N,K] row-major (C = A * B^T)      -- weight GEMMs, QK^T
//   BT=false: B is [K,N] row-major (C = A * B)        -- P*V
// 128x128x16 tiles, 8x8 per thread, smem double buffer, 1 sync per k-tile.
// blockIdx.z = batch, with linear strides sA/sB/sC.
// All dims are multiples of the tile sizes for this problem — no bounds checks.
// ---------------------------------------------------------------------------
template<bool BT>
__global__ __launch_bounds__(256, 2)
void sgemm_kernel(const float* __restrict__ Ag, const float* __restrict__ Bg,
                  float* __restrict__ Cg,
                  int M, int N, int K, int lda, int ldb, int ldc, float alpha,
                  long long sA, long long sB, long long sC)
{
    const float* A = Ag + blockIdx.z * sA;
    const float* B = Bg + blockIdx.z * sB;
    float*       C = Cg + blockIdx.z * sC;

    const int bm = blockIdx.y << 7;
    const int bn = blockIdx.x << 7;
    const int tid = threadIdx.x;

    __shared__ float As[2][16][132];
    __shared__ float Bs[2][16][132];

    const int ar = tid >> 2;          // 0..63 : row within A tile (and B tile if BT)
    const int ac = (tid & 3) << 2;    // 0,4,8,12 : k offset
    const int br = tid >> 5;          // 0..7  : k row within B tile (NN)
    const int bc = (tid & 31) << 2;   // 0..124: n offset (NN)

    const int wy = (tid >> 4) << 2;   // 0..60 thread row offset
    const int wx = (tid & 15) << 2;   // 0..60 thread col offset

    const float* Aptr = A + (long long)(bm + ar) * lda + ac;
    const float* Bptr = BT ? (B + (long long)(bn + ar) * ldb + ac)
                           : (B + (long long)br * ldb + bn + bc);

    float acc[8][8];
#pragma unroll
    for (int i = 0; i < 8; i++)
#pragma unroll
        for (int j = 0; j < 8; j++) acc[i][j] = 0.f;

    // prologue: load k-tile 0
    float4 pa0 = *(const float4*)(Aptr);
    float4 pa1 = *(const float4*)(Aptr + (long long)64 * lda);
    float4 pb0, pb1;
    if (BT) {
        pb0 = *(const float4*)(Bptr);
        pb1 = *(const float4*)(Bptr + (long long)64 * ldb);
    } else {
        pb0 = *(const float4*)(Bptr);
        pb1 = *(const float4*)(Bptr + (long long)8 * ldb);
    }
    As[0][ac+0][ar]    = pa0.x; As[0][ac+1][ar]    = pa0.y; As[0][ac+2][ar]    = pa0.z; As[0][ac+3][ar]    = pa0.w;
    As[0][ac+0][ar+64] = pa1.x; As[0][ac+1][ar+64] = pa1.y; As[0][ac+2][ar+64] = pa1.z; As[0][ac+3][ar+64] = pa1.w;
    if (BT) {
        Bs[0][ac+0][ar]    = pb0.x; Bs[0][ac+1][ar]    = pb0.y; Bs[0][ac+2][ar]    = pb0.z; Bs[0][ac+3][ar]    = pb0.w;
        Bs[0][ac+0][ar+64] = pb1.x; Bs[0][ac+1][ar+64] = pb1.y; Bs[0][ac+2][ar+64] = pb1.z; Bs[0][ac+3][ar+64] = pb1.w;
    } else {
        *(float4*)&Bs[0][br][bc]     = pb0;
        *(float4*)&Bs[0][br + 8][bc] = pb1;
    }
    __syncthreads();

    const int nk = K >> 4;
    for (int kt = 0; kt < nk; kt++) {
        const int buf = kt & 1;
        if (kt + 1 < nk) {  // prefetch next tile into registers
            const float* Ap = Aptr + (kt + 1) * 16;
            pa0 = *(const float4*)(Ap);
            pa1 = *(const float4*)(Ap + (long long)64 * lda);
            if (BT) {
                const float* Bp = Bptr + (kt + 1) * 16;
                pb0 = *(const float4*)(Bp);
                pb1 = *(const float4*)(Bp + (long long)64 * ldb);
            } else {
                const float* Bp = Bptr + (long long)(kt + 1) * 16 * ldb;
                pb0 = *(const float4*)(Bp);
                pb1 = *(const float4*)(Bp + (long long)8 * ldb);
            }
        }
#pragma unroll
        for (int k = 0; k < 16; k++) {
            float4 a0 = *(const float4*)&As[buf][k][wy];
            float4 a1 = *(const float4*)&As[buf][k][wy + 64];
            float4 b0 = *(const float4*)&Bs[buf][k][wx];
            float4 b1 = *(const float4*)&Bs[buf][k][wx + 64];
            float av[8] = {a0.x,a0.y,a0.z,a0.w,a1.x,a1.y,a1.z,a1.w};
            float bv[8] = {b0.x,b0.y,b0.z,b0.w,b1.x,b1.y,b1.z,b1.w};
#pragma unroll
            for (int i = 0; i < 8; i++)
#pragma unroll
                for (int j = 0; j < 8; j++)
                    acc[i][j] = fmaf(av[i], bv[j], acc[i][j]);
        }
        if (kt + 1 < nk) {  // store prefetched tile into other buffer
            const int nb = buf ^ 1;
            As[nb][ac+0][ar]    = pa0.x; As[nb][ac+1][ar]    = pa0.y; As[nb][ac+2][ar]    = pa0.z; As[nb][ac+3][ar]    = pa0.w;
            As[nb][ac+0][ar+64] = pa1.x; As[nb][ac+1][ar+64] = pa1.y; As[nb][ac+2][ar+64] = pa1.z; As[nb][ac+3][ar+64] = pa1.w;
            if (BT) {
                Bs[nb][ac+0][ar]    = pb0.x; Bs[nb][ac+1][ar]    = pb0.y; Bs[nb][ac+2][ar]    = pb0.z; Bs[nb][ac+3][ar]    = pb0.w;
                Bs[nb][ac+0][ar+64] = pb1.x; Bs[nb][ac+1][ar+64] = pb1.y; Bs[nb][ac+2][ar+64] = pb1.z; Bs[nb][ac+3][ar+64] = pb1.w;
            } else {
                *(float4*)&Bs[nb][br][bc]     = pb0;
                *(float4*)&Bs[nb][br + 8][bc] = pb1;
            }
            __syncthreads();
        }
    }

    // epilogue
#pragma unroll
    for (int i = 0; i < 8; i++) {
        const int row = bm + wy + (i & 3) + ((i >> 2) << 6);
        float* cp = C + (long long)row * ldc + bn + wx;
        float4 o0 = make_float4(acc[i][0]*alpha, acc[i][1]*alpha, acc[i][2]*alpha, acc[i][3]*alpha);
        float4 o1 = make_float4(acc[i][4]*alpha, acc[i][5]*alpha, acc[i][6]*alpha, acc[i][7]*alpha);
        *(float4*)(cp)      = o0;
        *(float4*)(cp + 64) = o1;
    }
}

// ---------------------------------------------------------------------------
// RMSNorm: out = x * rsqrt(mean(x^2) + eps) * w     (one block per row)
// ---------------------------------------------------------------------------
__global__ __launch_bounds__(256)
void rmsnorm_kernel(const float* __restrict__ in, const float* __restrict__ w,
                    float* __restrict__ out)
{
    const long long base = (long long)blockIdx.x * HID;
    const float4* xin = (const float4*)(in + base);
    float ss = 0.f;
#pragma unroll
    for (int i = threadIdx.x; i < HID/4; i += 256) {
        float4 v = xin[i];
        ss += v.x*v.x + v.y*v.y + v.z*v.z + v.w*v.w;
    }
    ss = blockReduceSum256(ss);
    const float r = rsqrtf(ss * (1.f/HID) + RMS_EPS);
#pragma unroll
    for (int i = threadIdx.x; i < HID/4; i += 256) {
        float4 v = xin[i];
        float4 ww = ((const float4*)w)[i];
        ((float4*)(out + base))[i] =
            make_float4(v.x*r*ww.x, v.y*r*ww.y, v.z*r*ww.z, v.w*r*ww.w);
    }
}

// x = x + rms(x, w)  (in place): x *= (1 + r*w)
__global__ __launch_bounds__(256)
void rmsadd_kernel(float* __restrict__ x, const float* __restrict__ w)
{
    const long long base = (long long)blockIdx.x * HID;
    float4* xp = (float4*)(x + base);
    float ss = 0.f;
#pragma unroll
    for (int i = threadIdx.x; i < HID/4; i += 256) {
        float4 v = xp[i];
        ss += v.x*v.x + v.y*v.y + v.z*v.z + v.w*v.w;
    }
    ss = blockReduceSum256(ss);
    const float r = rsqrtf(ss * (1.f/HID) + RMS_EPS);
#pragma unroll
    for (int i = threadIdx.x; i < HID/4; i += 256) {
        float4 v = xp[i];
        float4 ww = ((const float4*)w)[i];
        xp[i] = make_float4(v.x*(1.f + r*ww.x), v.y*(1.f + r*ww.y),
                            v.z*(1.f + r*ww.z), v.w*(1.f + r*ww.w));
    }
}

// ---------------------------------------------------------------------------
// RoPE (rotate-half) in place on [ROWS, HID] viewed as [row][head*128+d]
// ---------------------------------------------------------------------------
__global__ void rope_kernel(float* __restrict__ t)
{
    const int idx = blockIdx.x * blockDim.x + threadIdx.x;
    if (idx >= ROWS * NHEAD * (HDIM/2)) return;
    const int j   = idx & 63;
    const int h   = (idx >> 6) & (NHEAD - 1);
    const int row = idx >> 10;
    const int pos = row & (SEQ - 1);
    const float inv = (float)exp(-(double)(2*j) / (double)HDIM * log(10000.0));
    const float f = (float)pos * inv;
    float s_, c;
    sincosf(f, &s_, &c);
    float* p = t + (long long)row * HID + h * HDIM + j;
    const float q0 = p[0], q1 = p[HDIM/2];
    p[0]      = q0 * c - q1 * s_;
    p[HDIM/2] = q1 * c + q0 * s_;
}

// ---------------------------------------------------------------------------
// Softmax over rows of scores (scale pre-applied in GEMM alpha); adds mask.
// grid = (SEQ, BATCH*NHEAD), 256 threads, 8 elems/thread kept in registers.
// ---------------------------------------------------------------------------
__global__ __launch_bounds__(256)
void softmax_kernel(float* __restrict__ sc, const float* __restrict__ mask)
{
    float* p = sc + ((long long)blockIdx.y * SEQ + blockIdx.x) * SEQ;
    const float* mp = mask + (long long)blockIdx.x * SEQ;
    const int t = threadIdx.x * 8;
    float4 a = *(const float4*)(p + t);
    float4 b = *(const float4*)(p + t + 4);
    float4 ma = *(const float4*)(mp + t);
    float4 mb = *(const float4*)(mp + t + 4);
    a.x += ma.x; a.y += ma.y; a.z += ma.z; a.w += ma.w;
    b.x += mb.x; b.y += mb.y; b.z += mb.z; b.w += mb.w;
    float mx = fmaxf(fmaxf(fmaxf(a.x,a.y),fmaxf(a.z,a.w)),
                     fmaxf(fmaxf(b.x,b.y),fmaxf(b.z,b.w)));
    mx = blockReduceMax256(mx);
    a.x = expf(a.x - mx); a.y = expf(a.y - mx); a.z = expf(a.z - mx); a.w = expf(a.w - mx);
    b.x = expf(b.x - mx); b.y = expf(b.y - mx); b.z = expf(b.z - mx); b.w = expf(b.w - mx);
    float s = a.x + a.y + a.z + a.w + b.x + b.y + b.z + b.w;
    s = blockReduceSum256(s);
    const float invs = 1.f / s;
    a.x *= invs; a.y *= invs; a.z *= invs; a.w *= invs;
    b.x *= invs; b.y *= invs; b.z *= invs; b.w *= invs;
    *(float4*)(p + t)     = a;
    *(float4*)(p + t + 4) = b;
}

// ---------------------------------------------------------------------------
// Elementwise kernels (float4, one pass)
// ---------------------------------------------------------------------------
__device__ __forceinline__ float sigm(float z) { return 1.f / (1.f + expf(-z)); }

// out = sigmoid(g + bias) * h        (delta / highway)
__global__ void highway_kernel(const float* __restrict__ g, const float* __restrict__ hh,
                               const float* __restrict__ bias, float* __restrict__ out, int n4)
{
    const int i = blockIdx.x * blockDim.x + threadIdx.x;
    if (i >= n4) return;
    float4 gv = ((const float4*)g)[i];
    float4 hv = ((const float4*)hh)[i];
    float4 bv = ((const float4*)bias)[i & (HID/4 - 1)];
    ((float4*)out)[i] = make_float4(hv.x * sigm(gv.x + bv.x), hv.y * sigm(gv.y + bv.y),
                                    hv.z * sigm(gv.z + bv.z), hv.w * sigm(gv.w + bv.w));
}

// out = xm + mod + sigmoid(g + bias) * h
__global__ void combinex_kernel(const float* __restrict__ xm, const float* __restrict__ mod,
                                const float* __restrict__ g, const float* __restrict__ hh,
                                const float* __restrict__ bias, float* __restrict__ out, int n4)
{
    const int i = blockIdx.x * blockDim.x + threadIdx.x;
    if (i >= n4) return;
    float4 xv = ((const float4*)xm)[i];
    float4 mv = ((const float4*)mod)[i];
    float4 gv = ((const float4*)g)[i];
    float4 hv = ((const float4*)hh)[i];
    float4 bv = ((const float4*)bias)[i & (HID/4 - 1)];
    ((float4*)out)[i] = make_float4(xv.x + mv.x + hv.x * sigm(gv.x + bv.x),
                                    xv.y + mv.y + hv.y * sigm(gv.y + bv.y),
                                    xv.z + mv.z + hv.z * sigm(gv.z + bv.z),
                                    xv.w + mv.w + hv.w * sigm(gv.w + bv.w));
}

// g = silu(g) * u   (in place on g)
__global__ void silumul_kernel(float* __restrict__ g, const float* __restrict__ u, int n4)
{
    const int i = blockIdx.x * blockDim.x + threadIdx.x;
    if (i >= n4) return;
    float4 gv = ((float4*)g)[i];
    float4 uv = ((const float4*)u)[i];
    ((float4*)g)[i] = make_float4(gv.x * sigm(gv.x) * uv.x, gv.y * sigm(gv.y) * uv.y,
                                  gv.z * sigm(gv.z) * uv.z, gv.w * sigm(gv.w) * uv.w);
}

// out = a + b
__global__ void add2_kernel(const float* __restrict__ a, const float* __restrict__ b,
                            float* __restrict__ out, int n4)
{
    const int i = blockIdx.x * blockDim.x + threadIdx.x;
    if (i >= n4) return;
    float4 av = ((const float4*)a)[i];
    float4 bv = ((const float4*)b)[i];
    ((float4*)out)[i] = make_float4(av.x + bv.x, av.y + bv.y, av.z + bv.z, av.w + bv.w);
}

// ---------------------------------------------------------------------------
// Launch
// ---------------------------------------------------------------------------
extern "C" void kernel_launch(void* const* d_in, const int* in_sizes, int n_in,
                              void* d_out, int out_size)
{
    const float* x_mod      = (const float*)d_in[0];
    const float* x_back     = (const float*)d_in[1];
    const float* mask       = (const float*)d_in[2];
    const float* wq         = (const float*)d_in[3];
    const float* wk         = (const float*)d_in[4];
    const float* wv         = (const float*)d_in[5];
    const float* wo         = (const float*)d_in[6];
    const float* cross_ln_w = (const float*)d_in[7];
    const float* fb_w       = (const float*)d_in[8];
    const float* fb_g       = (const float*)d_in[9];
    const float* fb_gb      = (const float*)d_in[10];
    const float* dr_w       = (const float*)d_in[11];
    const float* dr_g       = (const float*)d_in[12];
    const float* dr_gb      = (const float*)d_in[13];
    const float* in_ln_w    = (const float*)d_in[14];
    const float* post_ln_w  = (const float*)d_in[15];
    const float* w_gate     = (const float*)d_in[16];
    const float* w_up       = (const float*)d_in[17];
    const float* w_down     = (const float*)d_in[18];

    float* outx = (float*)d_out;                       // x  first in the tuple
    float* outd = outx + (size_t)ROWS * HID;           // delta second

    float *qn,*q,*k,*v,*att,*mod,*t1,*t2,*x,*h,*gg,*uu,*sc;
    cudaGetSymbolAddress((void**)&qn,  g_qn);
    cudaGetSymbolAddress((void**)&q,   g_q);
    cudaGetSymbolAddress((void**)&k,   g_k);
    cudaGetSymbolAddress((void**)&v,   g_v);
    cudaGetSymbolAddress((void**)&att, g_att);
    cudaGetSymbolAddress((void**)&mod, g_mod);
    cudaGetSymbolAddress((void**)&t1,  g_t1);
    cudaGetSymbolAddress((void**)&t2,  g_t2);
    cudaGetSymbolAddress((void**)&x,   g_x);
    cudaGetSymbolAddress((void**)&h,   g_h);
    cudaGetSymbolAddress((void**)&gg,  g_gate);
    cudaGetSymbolAddress((void**)&uu,  g_up);
    cudaGetSymbolAddress((void**)&sc,  g_sc);

    const float ATT_SCALE = 0.08838834764831845f;   // 128^-0.5
    const int n4h = ROWS * HID / 4;                  // 2,097,152
    const int n4f = (int)((size_t)ROWS * FFD / 4);   // 8,388,608
    const dim3 B256(256);
    const dim3 gHH(HID/128, ROWS/128);               // 4096x2048 GEMM grid
    const dim3 gFF(FFD/128, ROWS/128);

    // ---- cross-attention inputs ----
    rmsnorm_kernel<<<ROWS, B256>>>(x_mod, cross_ln_w, qn);
    sgemm_kernel<true><<<gHH, B256>>>(qn,     wq, q, ROWS, HID, HID, HID, HID, HID, 1.f, 0, 0, 0);
    sgemm_kernel<true><<<gHH, B256>>>(x_back, wk, k, ROWS, HID, HID, HID, HID, HID, 1.f, 0, 0, 0);
    sgemm_kernel<true><<<gHH, B256>>>(x_back, wv, v, ROWS, HID, HID, HID, HID, HID, 1.f, 0, 0, 0);

    const int ropeN = ROWS * NHEAD * (HDIM/2);
    rope_kernel<<<(ropeN + 255)/256, B256>>>(q);
    rope_kernel<<<(ropeN + 255)/256, B256>>>(k);

    // ---- attention: scores = scale * Q K^T ; softmax(+mask) ; out = P V ----
    for (int b = 0; b < BATCH; b++) {
        dim3 gq(SEQ/128, SEQ/128, NHEAD);
        sgemm_kernel<true><<<gq, B256>>>(
            q + (size_t)b*SEQ*HID, k + (size_t)b*SEQ*HID, sc + (size_t)b*NHEAD*SEQ*SEQ,
            SEQ, SEQ, HDIM, HID, HID, SEQ, ATT_SCALE,
            128, 128, (long long)SEQ*SEQ);
    }
    softmax_kernel<<<dim3(SEQ, BATCH*NHEAD), B256>>>(sc, mask);
    for (int b = 0; b < BATCH; b++) {
        dim3 gp(HDIM/128, SEQ/128, NHEAD);
        sgemm_kernel<false><<<gp, B256>>>(
            sc + (size_t)b*NHEAD*SEQ*SEQ, v + (size_t)b*SEQ*HID, att + (size_t)b*SEQ*HID,
            SEQ, HDIM, SEQ, SEQ, HID, HID, 1.f,
            (long long)SEQ*SEQ, 128, 128);
    }
    sgemm_kernel<true><<<gHH, B256>>>(att, wo, mod, ROWS, HID, HID, HID, HID, HID, 1.f, 0, 0, 0);

    // ---- feedback highway -> delta (second output) ----
    sgemm_kernel<true><<<gHH, B256>>>(x_mod, fb_g, t1, ROWS, HID, HID, HID, HID, HID, 1.f, 0, 0, 0);
    sgemm_kernel<true><<<gHH, B256>>>(x_mod, fb_w, t2, ROWS, HID, HID, HID, HID, HID, 1.f, 0, 0, 0);
    highway_kernel<<<n4h/256, B256>>>(t1, t2, fb_gb, outd, n4h);

    // ---- driver highway, fused into x = x_mod + mod + drv ----
    sgemm_kernel<true><<<gHH, B256>>>(x_back, dr_g, t1, ROWS, HID, HID, HID, HID, HID, 1.f, 0, 0, 0);
    sgemm_kernel<true><<<gHH, B256>>>(x_back, dr_w, t2, ROWS, HID, HID, HID, HID, HID, 1.f, 0, 0, 0);
    combinex_kernel<<<n4h/256, B256>>>(x_mod, mod, t1, t2, dr_gb, x, n4h);

    // ---- decoder: x += rms(x); mlp on rms(x) ----
    rmsadd_kernel<<<ROWS, B256>>>(x, in_ln_w);
    rmsnorm_kernel<<<ROWS, B256>>>(x, post_ln_w, h);

    sgemm_kernel<true><<<gFF, B256>>>(h, w_gate, gg, ROWS, FFD, HID, HID, HID, FFD, 1.f, 0, 0, 0);
    sgemm_kernel<true><<<gFF, B256>>>(h, w_up,   uu, ROWS, FFD, HID, HID, HID, FFD, 1.f, 0, 0, 0);
    silumul_kernel<<<n4f/256, B256>>>(gg, uu, n4f);
    sgemm_kernel<true><<<gHH, B256>>>(gg, w_down, mod, ROWS, HID, FFD, FFD, FFD, HID, 1.f, 0, 0, 0);

    add2_kernel<<<n4h/256, B256>>>(x, mod, outx, n4h);
}

// round 4
// speedup vs baseline: 2.4644x; 2.4644x over previous
#include <cuda_runtime.h>
#include <cuda_bf16.h>
#include <cstdint>
#include <math.h>
using bf16 = __nv_bfloat16;
typedef long long ll;

#define BATCH 2
#define SEQ 2048
#define HID 2048
#define NHEAD 16
#define HDIM 128
#define FFD 8192
#define ROWS 4096
#define RMS_EPS 1e-5f
#define RH 8388608LL
#define H2 4194304LL
#define FF2 16777216LL
#define GGN 33554432LL
#define SCN 134217728LL

// ------------------------- scratch -------------------------
__device__ float g_q[RH], g_k[RH], g_v[RH], g_att[RH], g_mod[RH], g_t1[RH], g_t2[RH], g_x[RH];
__device__ float g_sc[SCN];
__device__ float g_gate[GGN], g_up[GGN];
__device__ bf16 g_wh[8*H2+3*FF2], g_wl[8*H2+3*FF2];
__device__ bf16 g_ah[8*RH+GGN],  g_al[8*RH+GGN];
__device__ bf16 g_ph[SCN], g_pl[SCN];

// weight arena offsets
#define OWQ  (0*H2)
#define OWK  (1*H2)
#define OWV  (2*H2)
#define OWO  (3*H2)
#define OFBW (4*H2)
#define OFBG (5*H2)
#define ODRW (6*H2)
#define ODRG (7*H2)
#define OWG  (8*H2)
#define OWU  (8*H2+FF2)
#define OWD  (8*H2+2*FF2)
// activation arena offsets
#define OQN  (0*RH)
#define OXB  (1*RH)
#define OXM  (2*RH)
#define OQ   (3*RH)
#define OK2  (4*RH)
#define OVT  (5*RH)
#define OATT (6*RH)
#define OHB  (7*RH)
#define OGG  (8*RH)

// ------------------------- PTX helpers -------------------------
__device__ __forceinline__ uint32_t smem_u32(const void* p) {
    uint32_t a;
    asm("{ .reg .u64 t; cvta.to.shared.u64 t, %1; cvt.u32.u64 %0, t; }" : "=r"(a) : "l"(p));
    return a;
}
__device__ __forceinline__ void cp16(uint32_t s, const void* g) {
    asm volatile("cp.async.cg.shared.global [%0], [%1], 16;" :: "r"(s), "l"(g));
}
__device__ __forceinline__ void cpcommit() { asm volatile("cp.async.commit_group;" ::: "memory"); }
__device__ __forceinline__ void cpwait0()  { asm volatile("cp.async.wait_group 0;" ::: "memory"); }
__device__ __forceinline__ void cpwait1()  { asm volatile("cp.async.wait_group 1;" ::: "memory"); }

__device__ __forceinline__ void ldsm4(uint32_t* r, uint32_t addr) {
    asm volatile("ldmatrix.sync.aligned.m8n8.x4.shared.b16 {%0,%1,%2,%3}, [%4];"
        : "=r"(r[0]), "=r"(r[1]), "=r"(r[2]), "=r"(r[3]) : "r"(addr));
}
__device__ __forceinline__ void mma16816(float* c, const uint32_t* a, uint32_t b0, uint32_t b1) {
    asm volatile("mma.sync.aligned.m16n8k16.row.col.f32.bf16.bf16.f32 "
        "{%0,%1,%2,%3}, {%4,%5,%6,%7}, {%8,%9}, {%0,%1,%2,%3};"
        : "+f"(c[0]), "+f"(c[1]), "+f"(c[2]), "+f"(c[3])
        : "r"(a[0]), "r"(a[1]), "r"(a[2]), "r"(a[3]), "r"(b0), "r"(b1));
}
__device__ __forceinline__ void split2(float x, bf16& h, bf16& l) {
    h = __float2bfloat16(x);
    l = __float2bfloat16(x - __bfloat162float(h));
}

// ---------------------------------------------------------------------------
// bf16x3 HMMA GEMM: C = alpha * (A @ B^T). A:[M,K] lda, B:[N,K] ldb, K-major.
// 128x128 CTA tile, KTILE=64, 3-stage cp.async, 8 warps (warp tile 32x64).
// Stage layout: Ah@0, Al@16K, Bh@32K, Bl@48K; 128B rows, XOR-16B swizzle.
// per-z offsets: off = (z/zdiv)*s?a + (z%zdiv)*s?b
// ---------------------------------------------------------------------------
#define STG 65536
#define TC_SMEM (3*STG)

__global__ __launch_bounds__(256)
void mma_gemm(const bf16* __restrict__ Ahg, const bf16* __restrict__ Alg,
              const bf16* __restrict__ Bhg, const bf16* __restrict__ Blg,
              float* __restrict__ Cg,
              int K, int lda, int ldb, int ldc, float alpha,
              int zdiv, ll sAa, ll sAb, ll sBa, ll sBb, ll sCa, ll sCb)
{
    extern __shared__ char smem_raw[];
    const uint32_t tiles = smem_u32(smem_raw);
    const int tid = threadIdx.x, wid = tid >> 5, lane = tid & 31;
    const int wm = wid & 3, wn = wid >> 2;     // 4x2 warp grid

    const int z = blockIdx.z;
    const ll aoff = (ll)(z / zdiv) * sAa + (ll)(z % zdiv) * sAb;
    const ll boff = (ll)(z / zdiv) * sBa + (ll)(z % zdiv) * sBb;
    const ll coff = (ll)(z / zdiv) * sCa + (ll)(z % zdiv) * sCb;
    const bf16* Ah = Ahg + aoff; const bf16* Al = Alg + aoff;
    const bf16* Bh = Bhg + boff; const bf16* Bl = Blg + boff;

    const int bm = blockIdx.y << 7, bn = blockIdx.x << 7;
    const int nk = K >> 6;

    auto load_stage = [&](int kt) {
        const uint32_t st = tiles + (uint32_t)(kt % 3) * STG;
        const ll kb = (ll)kt * 64;
#pragma unroll
        for (int i = tid; i < 1024; i += 256) {
            const int r = i >> 3, c = i & 7;
            const uint32_t sw = (uint32_t)r * 128u + (uint32_t)((c ^ (r & 7)) << 4);
            const ll ao = (ll)(bm + r) * lda + kb + c * 8;
            const ll bo = (ll)(bn + r) * ldb + kb + c * 8;
            cp16(st         + sw, Ah + ao);
            cp16(st + 16384 + sw, Al + ao);
            cp16(st + 32768 + sw, Bh + bo);
            cp16(st + 49152 + sw, Bl + bo);
        }
        cpcommit();
    };

    float acc[2][8][4];
#pragma unroll
    for (int i = 0; i < 2; i++)
#pragma unroll
        for (int j = 0; j < 8; j++)
#pragma unroll
            for (int t = 0; t < 4; t++) acc[i][j][t] = 0.f;

    // ldmatrix per-lane indices
    const int aRow  = wm * 32 + (lane & 15);   // + mt*16
    const int aCpar = lane >> 4;               // chunk parity
    const int bNadd = ((lane >> 4) << 3) + (lane & 7);  // + nt*16 (+ wn*64)
    const int bCpar = (lane >> 3) & 1;

    load_stage(0);
    if (nk > 1) load_stage(1);

    for (int kt = 0; kt < nk; kt++) {
        if (kt >= nk - 2) cpwait0(); else cpwait1();
        __syncthreads();
        if (kt + 2 < nk) load_stage(kt + 2);

        const uint32_t st = tiles + (uint32_t)(kt % 3) * STG;
#pragma unroll
        for (int ks = 0; ks < 4; ks++) {
            uint32_t ah[2][4], al[2][4];
#pragma unroll
            for (int mt = 0; mt < 2; mt++) {
                const int row = aRow + mt * 16;
                const int ch = ks * 2 + aCpar;
                const uint32_t ad = st + (uint32_t)row * 128u + (uint32_t)((ch ^ (row & 7)) << 4);
                ldsm4(ah[mt], ad);
                ldsm4(al[mt], ad + 16384);
            }
#pragma unroll
            for (int nt = 0; nt < 4; nt++) {
                const int row = wn * 64 + nt * 16 + bNadd;
                const int ch = ks * 2 + bCpar;
                const uint32_t bd = st + 32768u + (uint32_t)row * 128u + (uint32_t)((ch ^ (row & 7)) << 4);
                uint32_t bh[4], bl[4];
                ldsm4(bh, bd);
                ldsm4(bl, bd + 16384);
#pragma unroll
                for (int mt = 0; mt < 2; mt++) {
                    mma16816(acc[mt][nt*2],   ah[mt], bh[0], bh[1]);
                    mma16816(acc[mt][nt*2+1], ah[mt], bh[2], bh[3]);
                    mma16816(acc[mt][nt*2],   ah[mt], bl[0], bl[1]);
                    mma16816(acc[mt][nt*2+1], ah[mt], bl[2], bl[3]);
                    mma16816(acc[mt][nt*2],   al[mt], bh[0], bh[1]);
                    mma16816(acc[mt][nt*2+1], al[mt], bh[2], bh[3]);
                }
            }
        }
        __syncthreads();
    }

    // epilogue: c layout per mma tile: c0,c1 at (lane>>2, 2*(lane&3)); c2,c3 at row+8
    const int erow = bm + wm * 32 + (lane >> 2);
    const int ecol = bn + wn * 64 + (lane & 3) * 2;
#pragma unroll
    for (int mt = 0; mt < 2; mt++) {
#pragma unroll
        for (int j = 0; j < 8; j++) {
            float* p0 = Cg + coff + (ll)(erow + mt*16)     * ldc + ecol + j*8;
            float* p1 = Cg + coff + (ll)(erow + mt*16 + 8) * ldc + ecol + j*8;
            *(float2*)p0 = make_float2(acc[mt][j][0]*alpha, acc[mt][j][1]*alpha);
            *(float2*)p1 = make_float2(acc[mt][j][2]*alpha, acc[mt][j][3]*alpha);
        }
    }
}

// ------------------------- reductions -------------------------
__device__ __forceinline__ float wsum(float v) {
#pragma unroll
    for (int o = 16; o; o >>= 1) v += __shfl_xor_sync(0xffffffffu, v, o);
    return v;
}
__device__ __forceinline__ float wmax(float v) {
#pragma unroll
    for (int o = 16; o; o >>= 1) v = fmaxf(v, __shfl_xor_sync(0xffffffffu, v, o));
    return v;
}
__device__ __forceinline__ float bsum(float v) {
    __shared__ float sh[8];
    v = wsum(v); __syncthreads();
    if ((threadIdx.x & 31) == 0) sh[threadIdx.x >> 5] = v;
    __syncthreads();
    float r = 0.f;
#pragma unroll
    for (int i = 0; i < 8; i++) r += sh[i];
    return r;
}
__device__ __forceinline__ float bmax(float v) {
    __shared__ float sh[8];
    v = wmax(v); __syncthreads();
    if ((threadIdx.x & 31) == 0) sh[threadIdx.x >> 5] = v;
    __syncthreads();
    float r = sh[0];
#pragma unroll
    for (int i = 1; i < 8; i++) r = fmaxf(r, sh[i]);
    return r;
}

// ------------------------- elementwise kernels -------------------------
__global__ __launch_bounds__(256)
void split_kernel(const float* __restrict__ s, bf16* __restrict__ oh, bf16* __restrict__ ol, int n4)
{
    const int i = blockIdx.x * 256 + threadIdx.x;
    if (i >= n4) return;
    float4 v = ((const float4*)s)[i];
    bf16 h0,l0,h1,l1,h2,l2,h3,l3;
    split2(v.x,h0,l0); split2(v.y,h1,l1); split2(v.z,h2,l2); split2(v.w,h3,l3);
    ((__nv_bfloat162*)oh)[2*i]   = __nv_bfloat162(h0,h1);
    ((__nv_bfloat162*)oh)[2*i+1] = __nv_bfloat162(h2,h3);
    ((__nv_bfloat162*)ol)[2*i]   = __nv_bfloat162(l0,l1);
    ((__nv_bfloat162*)ol)[2*i+1] = __nv_bfloat162(l2,l3);
}

__global__ __launch_bounds__(256)
void rmsnorm_split(const float* __restrict__ in, const float* __restrict__ w,
                   bf16* __restrict__ oh, bf16* __restrict__ ol)
{
    const ll base = (ll)blockIdx.x * HID;
    const float4* xin = (const float4*)(in + base);
    float ss = 0.f;
    for (int i = threadIdx.x; i < HID/4; i += 256) {
        float4 v = xin[i];
        ss += v.x*v.x + v.y*v.y + v.z*v.z + v.w*v.w;
    }
    ss = bsum(ss);
    const float r = rsqrtf(ss * (1.f/HID) + RMS_EPS);
    for (int i = threadIdx.x; i < HID/4; i += 256) {
        float4 v = xin[i];
        float4 ww = ((const float4*)w)[i];
        bf16 h0,l0,h1,l1,h2,l2,h3,l3;
        split2(v.x*r*ww.x,h0,l0); split2(v.y*r*ww.y,h1,l1);
        split2(v.z*r*ww.z,h2,l2); split2(v.w*r*ww.w,h3,l3);
        ((__nv_bfloat162*)(oh + base))[2*i]   = __nv_bfloat162(h0,h1);
        ((__nv_bfloat162*)(oh + base))[2*i+1] = __nv_bfloat162(h2,h3);
        ((__nv_bfloat162*)(ol + base))[2*i]   = __nv_bfloat162(l0,l1);
        ((__nv_bfloat162*)(ol + base))[2*i+1] = __nv_bfloat162(l2,l3);
    }
}

__global__ __launch_bounds__(256)
void rmsadd_kernel(float* __restrict__ x, const float* __restrict__ w)
{
    const ll base = (ll)blockIdx.x * HID;
    float4* xp = (float4*)(x + base);
    float ss = 0.f;
    for (int i = threadIdx.x; i < HID/4; i += 256) {
        float4 v = xp[i];
        ss += v.x*v.x + v.y*v.y + v.z*v.z + v.w*v.w;
    }
    ss = bsum(ss);
    const float r = rsqrtf(ss * (1.f/HID) + RMS_EPS);
    for (int i = threadIdx.x; i < HID/4; i += 256) {
        float4 v = xp[i];
        float4 ww = ((const float4*)w)[i];
        xp[i] = make_float4(v.x*(1.f+r*ww.x), v.y*(1.f+r*ww.y), v.z*(1.f+r*ww.z), v.w*(1.f+r*ww.w));
    }
}

__global__ void rope_split(const float* __restrict__ src, bf16* __restrict__ oh, bf16* __restrict__ ol)
{
    const int idx = blockIdx.x * blockDim.x + threadIdx.x;
    if (idx >= ROWS * NHEAD * 64) return;
    const int j = idx & 63, h = (idx >> 6) & (NHEAD-1), row = idx >> 10;
    const int pos = row & (SEQ - 1);
    const float inv = (float)exp(-(double)(2*j) / (double)HDIM * log(10000.0));
    float s_, c;
    sincosf((float)pos * inv, &s_, &c);
    const ll p0 = (ll)row * HID + h * HDIM + j;
    const float q0 = src[p0], q1 = src[p0 + 64];
    bf16 hh, lll;
    split2(q0*c - q1*s_, hh, lll); oh[p0]    = hh; ol[p0]    = lll;
    split2(q1*c + q0*s_, hh, lll); oh[p0+64] = hh; ol[p0+64] = lll;
}

// V transpose-split: v[b*SEQ+s][h*128+d] -> vt[(z*128+d)*SEQ + s], z=b*16+h
__global__ void vtrans_kernel(const float* __restrict__ v, bf16* __restrict__ oh, bf16* __restrict__ ol)
{
    __shared__ float t[32][33];
    const int z = blockIdx.z, b = z >> 4, h = z & 15;
    const int s0 = blockIdx.x * 32, d0 = blockIdx.y * 32;
    const int tx = threadIdx.x, ty = threadIdx.y;
#pragma unroll
    for (int i = 0; i < 4; i++) {
        const int s = s0 + ty + i*8;
        t[ty + i*8][tx] = v[((ll)(b*SEQ + s)) * HID + h*HDIM + d0 + tx];
    }
    __syncthreads();
#pragma unroll
    for (int i = 0; i < 4; i++) {
        const int d = d0 + ty + i*8;
        const float x = t[tx][ty + i*8];
        bf16 hh, lll; split2(x, hh, lll);
        const ll o = ((ll)z * HDIM + d) * SEQ + s0 + tx;
        oh[o] = hh; ol[o] = lll;
    }
}

__global__ __launch_bounds__(256)
void softmax_split(const float* __restrict__ sc, const float* __restrict__ mask,
                   bf16* __restrict__ ph, bf16* __restrict__ pl)
{
    const ll off = ((ll)blockIdx.y * SEQ + blockIdx.x) * SEQ;
    const float* p = sc + off;
    const float* mp = mask + (ll)blockIdx.x * SEQ;
    const int t = threadIdx.x * 8;
    float v[8];
    float4 a = *(const float4*)(p + t), b = *(const float4*)(p + t + 4);
    float4 ma = *(const float4*)(mp + t), mb = *(const float4*)(mp + t + 4);
    v[0]=a.x+ma.x; v[1]=a.y+ma.y; v[2]=a.z+ma.z; v[3]=a.w+ma.w;
    v[4]=b.x+mb.x; v[5]=b.y+mb.y; v[6]=b.z+mb.z; v[7]=b.w+mb.w;
    float mx = v[0];
#pragma unroll
    for (int i = 1; i < 8; i++) mx = fmaxf(mx, v[i]);
    mx = bmax(mx);
    float s = 0.f;
#pragma unroll
    for (int i = 0; i < 8; i++) { v[i] = expf(v[i] - mx); s += v[i]; }
    s = bsum(s);
    const float inv = 1.f / s;
    __nv_bfloat162 hv[4], lv[4];
#pragma unroll
    for (int i = 0; i < 4; i++) {
        bf16 h0,l0,h1,l1;
        split2(v[2*i]*inv, h0, l0); split2(v[2*i+1]*inv, h1, l1);
        hv[i] = __nv_bfloat162(h0,h1); lv[i] = __nv_bfloat162(l0,l1);
    }
#pragma unroll
    for (int i = 0; i < 4; i++) {
        ((__nv_bfloat162*)(ph + off + t))[i] = hv[i];
        ((__nv_bfloat162*)(pl + off + t))[i] = lv[i];
    }
}

__device__ __forceinline__ float sigm(float z) { return 1.f / (1.f + expf(-z)); }

__global__ void highway_kernel(const float* __restrict__ g, const float* __restrict__ hh,
                               const float* __restrict__ bias, float* __restrict__ out, int n4)
{
    const int i = blockIdx.x * blockDim.x + threadIdx.x;
    if (i >= n4) return;
    float4 gv = ((const float4*)g)[i], hv = ((const float4*)hh)[i];
    float4 bv = ((const float4*)bias)[i & (HID/4 - 1)];
    ((float4*)out)[i] = make_float4(hv.x*sigm(gv.x+bv.x), hv.y*sigm(gv.y+bv.y),
                                    hv.z*sigm(gv.z+bv.z), hv.w*sigm(gv.w+bv.w));
}

__global__ void combinex_kernel(const float* __restrict__ xm, const float* __restrict__ mod,
                                const float* __restrict__ g, const float* __restrict__ hh,
                                const float* __restrict__ bias, float* __restrict__ out, int n4)
{
    const int i = blockIdx.x * blockDim.x + threadIdx.x;
    if (i >= n4) return;
    float4 xv = ((const float4*)xm)[i], mv = ((const float4*)mod)[i];
    float4 gv = ((const float4*)g)[i], hv = ((const float4*)hh)[i];
    float4 bv = ((const float4*)bias)[i & (HID/4 - 1)];
    ((float4*)out)[i] = make_float4(xv.x+mv.x+hv.x*sigm(gv.x+bv.x), xv.y+mv.y+hv.y*sigm(gv.y+bv.y),
                                    xv.z+mv.z+hv.z*sigm(gv.z+bv.z), xv.w+mv.w+hv.w*sigm(gv.w+bv.w));
}

__global__ void silumul_split(const float* __restrict__ g, const float* __restrict__ u,
                              bf16* __restrict__ oh, bf16* __restrict__ ol, int n4)
{
    const int i = blockIdx.x * blockDim.x + threadIdx.x;
    if (i >= n4) return;
    float4 gv = ((const float4*)g)[i], uv = ((const float4*)u)[i];
    float r0 = gv.x*sigm(gv.x)*uv.x, r1 = gv.y*sigm(gv.y)*uv.y;
    float r2 = gv.z*sigm(gv.z)*uv.z, r3 = gv.w*sigm(gv.w)*uv.w;
    bf16 h0,l0,h1,l1,h2,l2,h3,l3;
    split2(r0,h0,l0); split2(r1,h1,l1); split2(r2,h2,l2); split2(r3,h3,l3);
    ((__nv_bfloat162*)oh)[2*i]   = __nv_bfloat162(h0,h1);
    ((__nv_bfloat162*)oh)[2*i+1] = __nv_bfloat162(h2,h3);
    ((__nv_bfloat162*)ol)[2*i]   = __nv_bfloat162(l0,l1);
    ((__nv_bfloat162*)ol)[2*i+1] = __nv_bfloat162(l2,l3);
}

__global__ void add2_kernel(const float* __restrict__ a, const float* __restrict__ b,
                            float* __restrict__ out, int n4)
{
    const int i = blockIdx.x * blockDim.x + threadIdx.x;
    if (i >= n4) return;
    float4 av = ((const float4*)a)[i], bv = ((const float4*)b)[i];
    ((float4*)out)[i] = make_float4(av.x+bv.x, av.y+bv.y, av.z+bv.z, av.w+bv.w);
}

// ------------------------- launch -------------------------
extern "C" void kernel_launch(void* const* d_in, const int* in_sizes, int n_in,
                              void* d_out, int out_size)
{
    const float* x_mod = (const float*)d_in[0];
    const float* x_back= (const float*)d_in[1];
    const float* mask  = (const float*)d_in[2];
    const float* wq = (const float*)d_in[3];
    const float* wk = (const float*)d_in[4];
    const float* wv = (const float*)d_in[5];
    const float* wo = (const float*)d_in[6];
    const float* cross_ln_w = (const float*)d_in[7];
    const float* fb_w = (const float*)d_in[8];
    const float* fb_g = (const float*)d_in[9];
    const float* fb_gb= (const float*)d_in[10];
    const float* dr_w = (const float*)d_in[11];
    const float* dr_g = (const float*)d_in[12];
    const float* dr_gb= (const float*)d_in[13];
    const float* in_ln_w   = (const float*)d_in[14];
    const float* post_ln_w = (const float*)d_in[15];
    const float* w_gate = (const float*)d_in[16];
    const float* w_up   = (const float*)d_in[17];
    const float* w_down = (const float*)d_in[18];

    float* outx = (float*)d_out;
    float* outd = outx + (size_t)ROWS * HID;

    float *q,*k,*v,*att,*mod,*t1,*t2,*x,*sc,*gg,*uu;
    bf16 *wh,*wl,*ah,*al,*pph,*ppl;
    cudaGetSymbolAddress((void**)&q, g_q);   cudaGetSymbolAddress((void**)&k, g_k);
    cudaGetSymbolAddress((void**)&v, g_v);   cudaGetSymbolAddress((void**)&att, g_att);
    cudaGetSymbolAddress((void**)&mod, g_mod); cudaGetSymbolAddress((void**)&t1, g_t1);
    cudaGetSymbolAddress((void**)&t2, g_t2); cudaGetSymbolAddress((void**)&x, g_x);
    cudaGetSymbolAddress((void**)&sc, g_sc); cudaGetSymbolAddress((void**)&gg, g_gate);
    cudaGetSymbolAddress((void**)&uu, g_up);
    cudaGetSymbolAddress((void**)&wh, g_wh); cudaGetSymbolAddress((void**)&wl, g_wl);
    cudaGetSymbolAddress((void**)&ah, g_ah); cudaGetSymbolAddress((void**)&al, g_al);
    cudaGetSymbolAddress((void**)&pph, g_ph); cudaGetSymbolAddress((void**)&ppl, g_pl);

    cudaFuncSetAttribute(mma_gemm, cudaFuncAttributeMaxDynamicSharedMemorySize, TC_SMEM);

    const float ATT_SCALE = 0.08838834764831845f;
    const int n4h = (int)(RH/4), n4f = (int)(GGN/4), n4w = (int)(H2/4), n4ff = (int)(FF2/4);
    const dim3 B256(256);

    auto gemm = [&](const bf16* pah, const bf16* pal, const bf16* pbh, const bf16* pbl,
                    float* c, int M, int N, int K, int lda, int ldb, int ldc, float alpha,
                    int gz, int zdiv, ll saa, ll sab, ll sba, ll sbb, ll sca, ll scb) {
        dim3 g(N/128, M/128, gz);
        mma_gemm<<<g, 256, TC_SMEM>>>(pah, pal, pbh, pbl, c, K, lda, ldb, ldc, alpha,
                                      zdiv, saa, sab, sba, sbb, sca, scb);
    };

    // ---- splits of inputs ----
    split_kernel<<<n4h/256, B256>>>(x_mod,  ah+OXM, al+OXM, n4h);
    split_kernel<<<n4h/256, B256>>>(x_back, ah+OXB, al+OXB, n4h);
    rmsnorm_split<<<ROWS, B256>>>(x_mod, cross_ln_w, ah+OQN, al+OQN);
    split_kernel<<<n4w/256, B256>>>(wq,   wh+OWQ,  wl+OWQ,  n4w);
    split_kernel<<<n4w/256, B256>>>(wk,   wh+OWK,  wl+OWK,  n4w);
    split_kernel<<<n4w/256, B256>>>(wv,   wh+OWV,  wl+OWV,  n4w);
    split_kernel<<<n4w/256, B256>>>(wo,   wh+OWO,  wl+OWO,  n4w);
    split_kernel<<<n4w/256, B256>>>(fb_w, wh+OFBW, wl+OFBW, n4w);
    split_kernel<<<n4w/256, B256>>>(fb_g, wh+OFBG, wl+OFBG, n4w);
    split_kernel<<<n4w/256, B256>>>(dr_w, wh+ODRW, wl+ODRW, n4w);
    split_kernel<<<n4w/256, B256>>>(dr_g, wh+ODRG, wl+ODRG, n4w);
    split_kernel<<<n4ff/256, B256>>>(w_gate, wh+OWG, wl+OWG, n4ff);
    split_kernel<<<n4ff/256, B256>>>(w_up,   wh+OWU, wl+OWU, n4ff);
    split_kernel<<<n4ff/256, B256>>>(w_down, wh+OWD, wl+OWD, n4ff);

    // ---- q/k/v projections ----
    gemm(ah+OQN, al+OQN, wh+OWQ, wl+OWQ, q, ROWS, HID, HID, HID, HID, HID, 1.f, 1,1, 0,0,0,0,0,0);
    gemm(ah+OXB, al+OXB, wh+OWK, wl+OWK, k, ROWS, HID, HID, HID, HID, HID, 1.f, 1,1, 0,0,0,0,0,0);
    gemm(ah+OXB, al+OXB, wh+OWV, wl+OWV, v, ROWS, HID, HID, HID, HID, HID, 1.f, 1,1, 0,0,0,0,0,0);

    const int ropeN = ROWS * NHEAD * 64;
    rope_split<<<(ropeN+255)/256, B256>>>(q, ah+OQ,  al+OQ);
    rope_split<<<(ropeN+255)/256, B256>>>(k, ah+OK2, al+OK2);
    vtrans_kernel<<<dim3(SEQ/32, HDIM/32, BATCH*NHEAD), dim3(32,8)>>>(v, ah+OVT, al+OVT);

    // ---- attention ----
    gemm(ah+OQ, al+OQ, ah+OK2, al+OK2, sc, SEQ, SEQ, HDIM, HID, HID, SEQ, ATT_SCALE,
         BATCH*NHEAD, NHEAD, (ll)SEQ*HID, 128, (ll)SEQ*HID, 128,
         (ll)NHEAD*SEQ*SEQ, (ll)SEQ*SEQ);
    softmax_split<<<dim3(SEQ, BATCH*NHEAD), B256>>>(sc, mask, pph, ppl);
    gemm(pph, ppl, ah+OVT, al+OVT, att, SEQ, HDIM, SEQ, SEQ, SEQ, HID, 1.f,
         BATCH*NHEAD, NHEAD, (ll)NHEAD*SEQ*SEQ, (ll)SEQ*SEQ,
         (ll)NHEAD*HDIM*SEQ, (ll)HDIM*SEQ, (ll)SEQ*HID, 128);
    split_kernel<<<n4h/256, B256>>>(att, ah+OATT, al+OATT, n4h);
    gemm(ah+OATT, al+OATT, wh+OWO, wl+OWO, mod, ROWS, HID, HID, HID, HID, HID, 1.f, 1,1, 0,0,0,0,0,0);

    // ---- feedback highway -> delta ----
    gemm(ah+OXM, al+OXM, wh+OFBG, wl+OFBG, t1, ROWS, HID, HID, HID, HID, HID, 1.f, 1,1, 0,0,0,0,0,0);
    gemm(ah+OXM, al+OXM, wh+OFBW, wl+OFBW, t2, ROWS, HID, HID, HID, HID, HID, 1.f, 1,1, 0,0,0,0,0,0);
    highway_kernel<<<n4h/256, B256>>>(t1, t2, fb_gb, outd, n4h);

    // ---- driver highway + combine ----
    gemm(ah+OXB, al+OXB, wh+ODRG, wl+ODRG, t1, ROWS, HID, HID, HID, HID, HID, 1.f, 1,1, 0,0,0,0,0,0);
    gemm(ah+OXB, al+OXB, wh+ODRW, wl+ODRW, t2, ROWS, HID, HID, HID, HID, HID, 1.f, 1,1, 0,0,0,0,0,0);
    combinex_kernel<<<n4h/256, B256>>>(x_mod, mod, t1, t2, dr_gb, x, n4h);

    // ---- decoder ----
    rmsadd_kernel<<<ROWS, B256>>>(x, in_ln_w);
    rmsnorm_split<<<ROWS, B256>>>(x, post_ln_w, ah+OHB, al+OHB);
    gemm(ah+OHB, al+OHB, wh+OWG, wl+OWG, gg, ROWS, FFD, HID, HID, HID, FFD, 1.f, 1,1, 0,0,0,0,0,0);
    gemm(ah+OHB, al+OHB, wh+OWU, wl+OWU, uu, ROWS, FFD, HID, HID, HID, FFD, 1.f, 1,1, 0,0,0,0,0,0);
    silumul_split<<<n4f/256, B256>>>(gg, uu, ah+OGG, al+OGG, n4f);
    gemm(ah+OGG, al+OGG, wh+OWD, wl+OWD, mod, ROWS, HID, FFD, FFD, FFD, HID, 1.f, 1,1, 0,0,0,0,0,0);
    add2_kernel<<<n4h/256, B256>>>(x, mod, outx, n4h);
}